// round 10
// baseline (speedup 1.0000x reference)
#include <cuda_runtime.h>

// GAE backward scan as a parallel suffix scan of affine maps.
// gae_t = delta_t + c_t * gae_{t+1},  c_t = GAMMA*LMBDA*nd_t  (nd in {0,1})
//
// R10: R9 champion (48 warps/SM, 512thr, VPT=4, grid=4096, __stcs stores)
// with __ldcg loads (L2-only, bypass L1). L1 provides zero reuse here --
// each 128B line is consumed once by a single warp's LDG wavefront -- so
// skipping L1 allocation trims pass-through overhead (L1 was 41.5% busy).
// Hint matrix: plain/plain 28.83, cs/cs 28.58, plain/cs 28.19 (best).

#define GAMMA 0.99f
#define LMBDA 0.95f
#define KCOEF (GAMMA * LMBDA)   // 0.9405f

constexpr int T_LEN   = 2048;
constexpr int THREADS = 512;
constexpr int VPT     = T_LEN / THREADS;  // 4 elements per thread
constexpr int NWARP   = THREADS / 32;     // 16
constexpr size_t SMEM_BYTES = 64 * 1024;  // pins residency at 3 blocks/SM

__global__ __launch_bounds__(THREADS)
void gae_kernel(const float* __restrict__ reward,
                const int*   __restrict__ terminated,
                const float* __restrict__ value,
                const float* __restrict__ next_value,
                float*       __restrict__ adv_out,
                float*       __restrict__ ret_out)
{
    extern __shared__ float smem[];
    float* sA  = smem;            // [NWARP]
    float* sB  = smem + NWARP;    // [NWARP]
    float* gIn = smem + 2*NWARP;  // [NWARP]

    const int tid  = threadIdx.x;
    const int lane = tid & 31;
    const int warp = tid >> 5;

    const long long base = (long long)blockIdx.x * T_LEN + (long long)tid * VPT;

    // ---- L2-only loads (.cg): one float4/int4 per array, full sectors ----
    float4 rr = __ldcg(reinterpret_cast<const float4*>(reward     + base));
    float4 vv = __ldcg(reinterpret_cast<const float4*>(value      + base));
    float4 nn = __ldcg(reinterpret_cast<const float4*>(next_value + base));
    int4   tt = __ldcg(reinterpret_cast<const int4*>(terminated   + base));

    float v[VPT] = {vv.x, vv.y, vv.z, vv.w};
    float delta[VPT];
    unsigned mask = 0;
    // delta = r - v + GAMMA*nv*nd ; nd = !terminated
    delta[0] = (tt.x == 0) ? fmaf(GAMMA, nn.x, rr.x - vv.x) : (rr.x - vv.x);
    delta[1] = (tt.y == 0) ? fmaf(GAMMA, nn.y, rr.y - vv.y) : (rr.y - vv.y);
    delta[2] = (tt.z == 0) ? fmaf(GAMMA, nn.z, rr.z - vv.z) : (rr.z - vv.z);
    delta[3] = (tt.w == 0) ? fmaf(GAMMA, nn.w, rr.w - vv.w) : (rr.w - vv.w);
    mask |= (tt.x == 0 ? 1u : 0u) << 0;
    mask |= (tt.y == 0 ? 1u : 0u) << 1;
    mask |= (tt.z == 0 ? 1u : 0u) << 2;
    mask |= (tt.w == 0 ? 1u : 0u) << 3;

    // ---- Fold chunk into one affine composite (j=0 earliest/outermost) ----
    float A = 1.0f, B = 0.0f;
    #pragma unroll
    for (int j = 0; j < VPT; ++j) {
        B = fmaf(A, delta[j], B);
        A = ((mask >> j) & 1u) ? A * KCOEF : 0.0f;
    }

    // ---- Warp-level inclusive SUFFIX scan (self = earlier = outer) ----
    const unsigned FULL = 0xffffffffu;
    float Ai = A, Bi = B;
    #pragma unroll
    for (int off = 1; off < 32; off <<= 1) {
        float Ao = __shfl_down_sync(FULL, Ai, off);
        float Bo = __shfl_down_sync(FULL, Bi, off);
        if (lane + off < 32) {
            Bi = fmaf(Ai, Bo, Bi);
            Ai = Ai * Ao;
        }
    }
    // Exclusive within warp: composite of lanes (lane+1 .. 31)
    float Ae = __shfl_down_sync(FULL, Ai, 1);
    float Be = __shfl_down_sync(FULL, Bi, 1);
    if (lane == 31) { Ae = 1.0f; Be = 0.0f; }

    // ---- Cross-warp combine (16 warps) ----
    if (lane == 0) { sA[warp] = Ai; sB[warp] = Bi; }
    __syncthreads();
    if (tid < NWARP) {
        float g = 0.0f;
        #pragma unroll
        for (int w = NWARP - 1; w > 0; --w)
            if (w > tid) g = fmaf(sA[w], g, sB[w]);
        gIn[tid] = g;
    }
    __syncthreads();

    // Carry entering this thread's chunk (gae just past chunk end)
    float g = fmaf(Ae, gIn[warp], Be);

    // ---- Replay chunk backward, materialize advantages ----
    float adv[VPT];
    #pragma unroll
    for (int j = VPT - 1; j >= 0; --j) {
        g = ((mask >> j) & 1u) ? fmaf(KCOEF, g, delta[j]) : delta[j];
        adv[j] = g;
    }

    // ---- Evict-first stores: advantages, then returns = adv + value ----
    float4 av, rt;
    av.x = adv[0]; av.y = adv[1]; av.z = adv[2]; av.w = adv[3];
    rt.x = av.x + v[0];
    rt.y = av.y + v[1];
    rt.z = av.z + v[2];
    rt.w = av.w + v[3];
    __stcs(reinterpret_cast<float4*>(adv_out + base), av);
    __stcs(reinterpret_cast<float4*>(ret_out + base), rt);
}

extern "C" void kernel_launch(void* const* d_in, const int* in_sizes, int n_in,
                              void* d_out, int out_size)
{
    const float* reward     = (const float*)d_in[0];
    const int*   terminated = (const int*)  d_in[1];
    const float* value      = (const float*)d_in[2];
    const float* next_value = (const float*)d_in[3];

    const int n = in_sizes[0];          // B * T
    const int B = n / T_LEN;

    float* adv_out = (float*)d_out;          // advantages: first n elements
    float* ret_out = (float*)d_out + n;      // returns:    next n elements

    cudaFuncSetAttribute(gae_kernel,
                         cudaFuncAttributeMaxDynamicSharedMemorySize,
                         (int)SMEM_BYTES);

    gae_kernel<<<B, THREADS, SMEM_BYTES>>>(reward, terminated, value,
                                           next_value, adv_out, ret_out);
}